// round 15
// baseline (speedup 1.0000x reference)
#include <cuda_runtime.h>
#include <cuda_fp16.h>
#include <mma.h>
#include <cstdint>
#include <cstddef>

using namespace nvcuda;

#define Tt 10
#define Bb 16
#define Ss 200
#define Dd 768
#define K5 3840            // 5*D
#define NPAD 2432          // 1216 (fwd block) + 1216 (bwd block)
#define NDIRBASE 1216
#define Mm 32000           // T*S*B
#define KH 320             // padded recurrent K
#define LDW 344            // Whh staging stride (halves)
#define LDA 20             // accS stride (floats)
#define NCTA_L 75

// ---------------- device scratch (allocation-free) ----------------
__device__ __half g_X[(size_t)Mm * K5];      // 245.8 MB fp16
__device__ __half g_W[(size_t)NPAD * K5];    // 18.7 MB fp16
__device__ float g_C[(size_t)Mm * NPAD];     // 311.3 MB
__device__ float g_ws[Tt * Bb * Ss];
__device__ float g_we[Tt * Bb * Ss];
__device__ float g_wbs[Bb * Ss];
__device__ float g_wbe[Bb * Ss];
__device__ float g_y[(size_t)Tt * Ss * Bb * 600];  // [t][s][b][2H]
// stamped h words: (step<<16)|fp16  layout [dir][parity][k][b]
__device__ unsigned g_h32[2 * 2 * KH * Bb];  // 160 KB

// ---------------- helpers ----------------
__device__ __forceinline__ uint32_t smem_u32(const void* p) {
    uint32_t a;
    asm("{ .reg .u64 t; cvta.to.shared.u64 t, %1; cvt.u32.u64 %0, t; }" : "=r"(a) : "l"(p));
    return a;
}
__device__ __forceinline__ void cp16(uint32_t d, const void* s) {
    asm volatile("cp.async.cg.shared.global [%0], [%1], 16;" :: "r"(d), "l"(s) : "memory");
}
__device__ __forceinline__ unsigned ldrelax(const unsigned* p) {
    unsigned x;
    asm volatile("ld.global.relaxed.gpu.u32 %0, [%1];" : "=r"(x) : "l"(p) : "memory");
    return x;
}
__device__ __forceinline__ void strelax(unsigned* p, unsigned v) {
    asm volatile("st.global.relaxed.gpu.u32 [%0], %1;" :: "l"(p), "r"(v) : "memory");
}

// ---------------- kernel 0: init (reset stamps each launch/replay) -----------
__global__ void k_init() {
    int i = threadIdx.x + blockIdx.x * blockDim.x;
    for (int e = i; e < 2 * 2 * KH * Bb; e += gridDim.x * blockDim.x)
        g_h32[e] = 0u;   // stamp 0, h = +0.0h
}

// ---------------- kernel 1: fused attention weights ----------------
__global__ void k_weights(const float* __restrict__ sp, const float* __restrict__ ep,
                          const float* __restrict__ cp,
                          const float* __restrict__ bsp, const float* __restrict__ bep,
                          const float* __restrict__ bcp,
                          const float* __restrict__ um, const float* __restrict__ nm,
                          const float* __restrict__ am) {
    int idx = blockIdx.x * blockDim.x + threadIdx.x;
    if (idx >= Tt * Bb * Ss) return;
    int t = idx / (Bb * Ss);
    int r = idx % (Bb * Ss);
    int b = r / Ss;
    int s = r % Ss;
    // masks are [B,T,S]
    float amv = am[(b * Tt + t) * Ss + s];
    float umv = um[(b * Tt + t) * Ss + s];
    float nmv = nm[(b * Tt + t) * Ss + s];
    const float* c = cp + (t * Bb + b) * 4;
    float wb = amv * c[0] + umv * c[1] + nmv * c[2];
    g_ws[idx] = sp[idx] * wb;
    g_we[idx] = ep[idx] * wb;
    if (t == 0) {
        const float* bc = bcp + b * 4;
        float wbb = amv * bc[0] + umv * bc[1] + nmv * bc[2];
        g_wbs[b * Ss + s] = bsp[b * Ss + s] * wbb;
        g_wbe[b * Ss + s] = bep[b * Ss + s] * wbb;
    }
}

// ---------------- kernel 2: stacked + gate-permuted fp16 Wih -----------------
__global__ void k_wpad(const float* __restrict__ wf, const float* __restrict__ wb) {
    int rrow = blockIdx.x;
    int dir = rrow >= NDIRBASE;
    int rp = dir ? rrow - NDIRBASE : rrow;
    const float* src = nullptr;
    if (rp < 1200) {
        int tile = rp >> 4, gate = (rp >> 2) & 3, cc = rp & 3;
        int srow = gate * 300 + tile * 4 + cc;
        src = (dir ? wb : wf) + (size_t)srow * K5;
    }
    __half* dst = g_W + (size_t)rrow * K5;
    for (int c = threadIdx.x * 4; c < K5; c += blockDim.x * 4) {
        float4 v = make_float4(0.f, 0.f, 0.f, 0.f);
        if (src) v = *(const float4*)(src + c);
        __half2 a = __floats2half2_rn(v.x, v.y);
        __half2 b2 = __floats2half2_rn(v.z, v.w);
        *(__half2*)(dst + c) = a;
        *(__half2*)(dst + c + 2) = b2;
    }
}

// ---------------- kernel 3: build X (fp16) ----------------
__global__ void k_xbuild(const float* __restrict__ seq) {
    int m = blockIdx.x;          // ((t*200+s)*16+b)
    int b = m & 15;
    int ts = m >> 4;
    int s = ts % Ss;
    int t = ts / Ss;
    int tp = (t > 0) ? (t - 1) : 0;
    int c = threadIdx.x * 4;     // 192 threads -> 768 cols
    const float4 sv = *(const float4*)(seq + (((size_t)(t * Bb + b) * Ss + s) * Dd) + c);
    const float4 pv = *(const float4*)(seq + (((size_t)(tp * Bb + b) * Ss + s) * Dd) + c);
    int widx = (t * Bb + b) * Ss + s;
    float w1 = g_ws[widx], w2 = g_we[widx];
    float wp1, wp2;
    if (t > 0) {
        int pidx = ((t - 1) * Bb + b) * Ss + s;
        wp1 = g_ws[pidx];
        wp2 = g_we[pidx];
    } else {
        wp1 = g_wbs[b * Ss + s];
        wp2 = g_wbe[b * Ss + s];
    }
    __half* X = g_X + (size_t)m * K5 + c;
#define R4(off, a, wgt) do { \
        __half2 _h0 = __floats2half2_rn((a).x * (wgt), (a).y * (wgt)); \
        __half2 _h1 = __floats2half2_rn((a).z * (wgt), (a).w * (wgt)); \
        *(__half2*)(X + (off)) = _h0; \
        *(__half2*)(X + (off) + 2) = _h1; } while (0)
    R4(0,    sv, 1.f);
    R4(768,  sv, w1);
    R4(1536, sv, w2);
    R4(2304, pv, wp1);
    R4(3072, pv, wp2);
#undef R4
}

// ---------------- kernel 4: pipelined fp16 wmma GEMM  C = X * W^T ------------
#define GP2 40
#define STAGEH (2 * 128 * GP2)         // halves per stage (A + B)
#define GSMEM (3 * STAGEH * 2)         // 61440 B -> 2 CTAs/SM
#define NK (K5 / 32)                   // 120 k-tiles

__global__ void __launch_bounds__(256) k_gemm2() {
    extern __shared__ __half smh[];
    int tid = threadIdx.x;
    int mt = blockIdx.y, nt = blockIdx.x;
    uint32_t sbase = smem_u32(smh);

    int wid = tid >> 5;
    int wy = wid >> 1, wx = wid & 1;   // 4x2 warps; warp tile 32x64

    int lrow0 = tid >> 2;              // 64 rows per pass, 2 passes
    int lc4 = tid & 3;                 // 4 chunks of 8 halves per row

    const __half* AG = g_X + (size_t)(mt * 128) * K5;
    const __half* BG = g_W + (size_t)(nt * 128) * K5;

    wmma::fragment<wmma::accumulator, 16, 16, 16, float> acc[2][4];
#pragma unroll
    for (int i = 0; i < 2; ++i)
#pragma unroll
        for (int j = 0; j < 4; ++j) wmma::fill_fragment(acc[i][j], 0.f);

#define LOADSTAGE(kt, st) do { \
        uint32_t sa = sbase + (st) * STAGEH * 2; \
        uint32_t sbb = sa + 128 * GP2 * 2; \
        int kof = (kt) * 32 + lc4 * 8; \
        _Pragma("unroll") \
        for (int i = 0; i < 2; ++i) { \
            int row = lrow0 + i * 64; \
            cp16(sa  + (row * GP2 + lc4 * 8) * 2, AG + (size_t)row * K5 + kof); \
            cp16(sbb + (row * GP2 + lc4 * 8) * 2, BG + (size_t)row * K5 + kof); \
        } \
        asm volatile("cp.async.commit_group;" ::: "memory"); \
    } while (0)

    LOADSTAGE(0, 0);
    LOADSTAGE(1, 1);

    for (int kt = 0; kt < NK; ++kt) {
        int st = kt % 3;
        asm volatile("cp.async.wait_group 1;" ::: "memory");
        __syncthreads();
        if (kt + 2 < NK) {
            LOADSTAGE(kt + 2, (kt + 2) % 3);
        } else {
            asm volatile("cp.async.commit_group;" ::: "memory");
        }
        const __half* As = smh + st * STAGEH;
        const __half* Bs = As + 128 * GP2;
#pragma unroll
        for (int ks = 0; ks < 2; ++ks) {
            wmma::fragment<wmma::matrix_a, 16, 16, 16, half, wmma::row_major> a0, a1;
            wmma::load_matrix_sync(a0, As + (wy * 32) * GP2 + ks * 16, GP2);
            wmma::load_matrix_sync(a1, As + (wy * 32 + 16) * GP2 + ks * 16, GP2);
#pragma unroll
            for (int j = 0; j < 4; ++j) {
                wmma::fragment<wmma::matrix_b, 16, 16, 16, half, wmma::col_major> bf;
                wmma::load_matrix_sync(bf, Bs + (wx * 64 + j * 16) * GP2 + ks * 16, GP2);
                wmma::mma_sync(acc[0][j], a0, bf, acc[0][j]);
                wmma::mma_sync(acc[1][j], a1, bf, acc[1][j]);
            }
        }
    }
#undef LOADSTAGE

#pragma unroll
    for (int i = 0; i < 2; ++i)
#pragma unroll
        for (int j = 0; j < 4; ++j) {
            float* cp = g_C + (size_t)(mt * 128 + wy * 32 + i * 16) * NPAD
                        + nt * 128 + wx * 64 + j * 16;
            wmma::store_matrix_sync(cp, acc[i][j], NPAD, wmma::mem_row_major);
        }
}

// ---------------- kernel 5: stamped-word persistent LSTM scan ----------------
// Each h value is a self-validating u32 (step<<16 | fp16): the store IS the
// sync. No flags, no release drains, no fences. Warps poll their own k-slice
// into per-warp smem staging, then MMA with register-resident Whh B-frags.
__device__ __forceinline__ float sigm(float x) {
    return 1.f / (1.f + __expf(-x));
}
__device__ __forceinline__ float tanh_fast(float x) {
    x = fminf(fmaxf(x, -15.f), 15.f);
    float e = __expf(-2.f * x);
    return (1.f - e) / (1.f + e);
}

__global__ void __launch_bounds__(256, 1) k_lstm(
        const float* __restrict__ whf, const float* __restrict__ whb,
        const float* __restrict__ bihf, const float* __restrict__ bhhf,
        const float* __restrict__ bihb, const float* __restrict__ bhhb) {
    __shared__ __half WhhS[2 * 16 * LDW];                 // prologue staging only
    __shared__ float accS[8 * 16 * LDA];
    __shared__ float bS[32];
    __shared__ __align__(32) unsigned short stg[8 * 1280];  // per-warp A staging [k][b]

    int tid = threadIdx.x;
    int tile = blockIdx.x;                   // owns h-cols [4*tile, 4*tile+4)

    // prologue: Whh slices (gate-permuted, fp16), bias, zero staging
    for (int e = tid; e < 2 * 16 * LDW; e += 256) {
        int k = e % LDW;
        int lrr = (e / LDW) & 15;
        int dir = e / (16 * LDW);
        int gate = lrr >> 2, cc = lrr & 3;
        int srow = gate * 300 + tile * 4 + cc;
        float v = 0.f;
        if (k < 300) v = (dir ? whb : whf)[srow * 300 + k];
        WhhS[e] = __float2half(v);
    }
    for (int e = tid; e < 8 * 1280; e += 256) stg[e] = 0;
    if (tid < 32) {
        int dir = tid >> 4, lrr = tid & 15;
        int gate = lrr >> 2, cc = lrr & 3;
        int srow = gate * 300 + tile * 4 + cc;
        bS[tid] = dir ? (bihb[srow] + bhhb[srow]) : (bihf[srow] + bhhf[srow]);
    }
    __syncthreads();

    int wid = tid >> 5, lane = tid & 31;
    int dirw = wid >> 2, kq = wid & 3;       // warps 0-3 fwd, 4-7 bwd; k-split x4
    int edir = tid >> 6, eidx = tid & 63, ecc = eidx >> 4, eb = eidx & 15;

    // register-resident B fragments (constant across all 2000 steps)
    wmma::fragment<wmma::matrix_b, 16, 16, 16, half, wmma::col_major> Bf[5];
#pragma unroll
    for (int i = 0; i < 5; ++i)
        wmma::load_matrix_sync(Bf[i], WhhS + dirw * 16 * LDW + kq * 80 + i * 16, LDW);
    __syncthreads();

    unsigned short* mystg = stg + wid * 1280;    // [k_local*16 + b]
    int limit = (kq == 3) ? 30 : 40;             // entries covering real k<300

    float creg = 0.f;
    float bi = 0.f, bf2 = 0.f, bg = 0.f, bo = 0.f;
    if (tid < 128) {
        bi  = bS[edir * 16 + 0 + ecc];
        bf2 = bS[edir * 16 + 4 + ecc];
        bg  = bS[edir * 16 + 8 + ecc];
        bo  = bS[edir * 16 + 12 + ecc];
    }

    // z double buffer: prefetch step 0
    float z0 = 0.f, z1 = 0.f, z2 = 0.f, z3 = 0.f;
    float n0 = 0.f, n1 = 0.f, n2 = 0.f, n3 = 0.f;
    if (tid < 128) {
        int pos0 = edir ? (Ss - 1) : 0;
        const float* crow = g_C + ((size_t)pos0 * Bb + eb) * NPAD
                            + (edir ? NDIRBASE : 0) + tile * 16;
        n0 = crow[0 + ecc]; n1 = crow[4 + ecc]; n2 = crow[8 + ecc]; n3 = crow[12 + ecc];
    }

    for (int g = 0; g < Tt * Ss; ++g) {
        int t = g / Ss, s = g % Ss;
        int parity = g & 1;
        z0 = n0; z1 = n1; z2 = n2; z3 = n3;

        // stamped poll+load: accept words with stamp==g straight into staging
        {
            unsigned want = (unsigned)g;
            const unsigned* base = g_h32 + ((size_t)(dirw * 2 + parity) * KH + kq * 80) * Bb;
            uint64_t pend = 0;
#pragma unroll
            for (int i = 0; i < 40; ++i) {
                if (i < limit) {
                    unsigned x = ldrelax(base + i * 32 + lane);
                    if ((x >> 16) == want) mystg[i * 32 + lane] = (unsigned short)x;
                    else pend |= (1ull << i);
                }
            }
            while (pend) {
                uint64_t m = pend;
                do {
                    int i = __ffsll((long long)m) - 1;
                    m &= m - 1;
                    unsigned x = ldrelax(base + i * 32 + lane);
                    if ((x >> 16) == want) {
                        mystg[i * 32 + lane] = (unsigned short)x;
                        pend &= ~(1ull << i);
                    }
                } while (m);
            }
            __syncwarp();
        }

        // recurrent matmul: A col-major from staging (ldm=16), B from registers
        {
            wmma::fragment<wmma::accumulator, 16, 16, 16, float> acc;
            wmma::fill_fragment(acc, 0.f);
#pragma unroll
            for (int i = 0; i < 5; ++i) {
                wmma::fragment<wmma::matrix_a, 16, 16, 16, half, wmma::col_major> af;
                wmma::load_matrix_sync(af, (const __half*)mystg + i * 256, 16);
                wmma::mma_sync(acc, af, Bf[i], acc);
            }
            wmma::store_matrix_sync(accS + wid * 16 * LDA, acc, LDA, wmma::mem_row_major);
        }

        // prefetch next step's z
        if (tid < 128 && g + 1 < Tt * Ss) {
            int gn = g + 1;
            int tn = gn / Ss, sn = gn % Ss;
            int posn = edir ? (Ss - 1 - sn) : sn;
            const float* crow = g_C + ((size_t)(tn * Ss + posn) * Bb + eb) * NPAD
                                + (edir ? NDIRBASE : 0) + tile * 16;
            n0 = crow[0 + ecc]; n1 = crow[4 + ecc]; n2 = crow[8 + ecc]; n3 = crow[12 + ecc];
        }
        __syncthreads();   // accS visible to gate threads

        // gates + state update; publish stamped h words (the store IS the sync)
        float hval = 0.f;
        if (tid < 128) {
            const float* ab = accS + edir * 4 * 16 * LDA + eb * LDA;
            const int W1 = 16 * LDA, W2 = 32 * LDA, W3 = 48 * LDA;
            float zi = z0 + bi  + ab[0 + ecc]  + ab[W1 + 0 + ecc]  + ab[W2 + 0 + ecc]  + ab[W3 + 0 + ecc];
            float zf = z1 + bf2 + ab[4 + ecc]  + ab[W1 + 4 + ecc]  + ab[W2 + 4 + ecc]  + ab[W3 + 4 + ecc];
            float zg = z2 + bg  + ab[8 + ecc]  + ab[W1 + 8 + ecc]  + ab[W2 + 8 + ecc]  + ab[W3 + 8 + ecc];
            float zo = z3 + bo  + ab[12 + ecc] + ab[W1 + 12 + ecc] + ab[W2 + 12 + ecc] + ab[W3 + 12 + ecc];
            float ig = sigm(zi);
            float fg = sigm(zf);
            float gg = tanh_fast(zg);
            float og = sigm(zo);
            creg = fg * creg + ig * gg;
            hval = og * tanh_fast(creg);
            int jh = tile * 4 + ecc;
            unsigned word = ((unsigned)(g + 1) << 16)
                          | (unsigned)__half_as_ushort(__float2half(hval));
            strelax(g_h32 + ((size_t)(edir * 2 + (parity ^ 1)) * KH + jh) * Bb + eb, word);
        }
        __syncthreads();   // accS reuse guard for next step's MMA stores

        // y write (off critical path)
        if (tid < 128) {
            int pos = edir ? (Ss - 1 - s) : s;
            int jh = tile * 4 + ecc;
            g_y[((size_t)(t * Ss + pos) * Bb + eb) * 600 + edir * 300 + jh] = hval;
        }
    }
}

// ---------------- kernel 6: classifier ----------------
__global__ void k_cls(const float* __restrict__ W, const float* __restrict__ bc,
                      float* __restrict__ out) {
    int t = blockIdx.x >> 4, b = blockIdx.x & 15;
    float a0 = 0.f, a1 = 0.f, a2 = 0.f, a3 = 0.f;
    const size_t NW = 120000;
    for (int idx = threadIdx.x; idx < (int)NW; idx += 256) {
        int s = idx / 600, c = idx % 600;
        float yv = g_y[((size_t)(t * Ss + s) * Bb + b) * 600 + c];
        yv = fmaxf(yv, 0.f);
        a0 += yv * W[idx];
        a1 += yv * W[NW + idx];
        a2 += yv * W[2 * NW + idx];
        a3 += yv * W[3 * NW + idx];
    }
#pragma unroll
    for (int off = 16; off; off >>= 1) {
        a0 += __shfl_down_sync(0xFFFFFFFFu, a0, off);
        a1 += __shfl_down_sync(0xFFFFFFFFu, a1, off);
        a2 += __shfl_down_sync(0xFFFFFFFFu, a2, off);
        a3 += __shfl_down_sync(0xFFFFFFFFu, a3, off);
    }
    __shared__ float rs[8][4];
    if ((threadIdx.x & 31) == 0) {
        int w = threadIdx.x >> 5;
        rs[w][0] = a0; rs[w][1] = a1; rs[w][2] = a2; rs[w][3] = a3;
    }
    __syncthreads();
    if (threadIdx.x < 4) {
        float sv = bc[threadIdx.x];
#pragma unroll
        for (int w = 0; w < 8; ++w) sv += rs[w][threadIdx.x];
        out[blockIdx.x * 4 + threadIdx.x] = sv;
    }
}

// ---------------- host launcher ----------------
extern "C" void kernel_launch(void* const* d_in, const int* in_sizes, int n_in,
                              void* d_out, int out_size) {
    const float* seq  = (const float*)d_in[1];
    const float* sp   = (const float*)d_in[2];
    const float* ep   = (const float*)d_in[3];
    const float* cp   = (const float*)d_in[4];
    const float* bsp  = (const float*)d_in[5];
    const float* bep  = (const float*)d_in[6];
    const float* bcp  = (const float*)d_in[7];
    const float* um   = (const float*)d_in[8];
    const float* nm   = (const float*)d_in[9];
    const float* am   = (const float*)d_in[10];
    const float* wihf = (const float*)d_in[11];
    const float* whhf = (const float*)d_in[12];
    const float* bihf = (const float*)d_in[13];
    const float* bhhf = (const float*)d_in[14];
    const float* wihb = (const float*)d_in[15];
    const float* whhb = (const float*)d_in[16];
    const float* bihb = (const float*)d_in[17];
    const float* bhhb = (const float*)d_in[18];
    const float* wcls = (const float*)d_in[19];
    const float* bcls = (const float*)d_in[20];
    float* out = (float*)d_out;

    cudaFuncSetAttribute(k_gemm2, cudaFuncAttributeMaxDynamicSharedMemorySize, GSMEM);

    k_init<<<48, 256>>>();
    k_weights<<<(Tt * Bb * Ss + 255) / 256, 256>>>(sp, ep, cp, bsp, bep, bcp, um, nm, am);
    k_wpad<<<NPAD, 256>>>(wihf, wihb);
    k_xbuild<<<Mm, 192>>>(seq);
    dim3 gg(NPAD / 128, Mm / 128);
    k_gemm2<<<gg, 256, GSMEM>>>();
    k_lstm<<<NCTA_L, 256>>>(whhf, whhb, bihf, bhhf, bihb, bhhb);
    k_cls<<<Tt * Bb, 256>>>(wcls, bcls, out);
}

// round 16
// speedup vs baseline: 2.0961x; 2.0961x over previous
#include <cuda_runtime.h>
#include <cuda_fp16.h>
#include <mma.h>
#include <cstdint>
#include <cstddef>

using namespace nvcuda;

#define Tt 10
#define Bb 16
#define Ss 200
#define Dd 768
#define K5 3840            // 5*D
#define NPAD 2432          // 1216 (fwd block) + 1216 (bwd block)
#define NDIRBASE 1216
#define Mm 32000           // T*S*B
#define KH 320             // padded recurrent K
#define LDW 344            // Whh staging stride (halves)
#define LDA 20             // accS stride (floats)
#define NCTA_L 75

// ---------------- device scratch (allocation-free) ----------------
__device__ __half g_X[(size_t)Mm * K5];      // 245.8 MB fp16
__device__ __half g_W[(size_t)NPAD * K5];    // 18.7 MB fp16
__device__ float g_C[(size_t)Mm * NPAD];     // 311.3 MB
__device__ float g_ws[Tt * Bb * Ss];
__device__ float g_we[Tt * Bb * Ss];
__device__ float g_wbs[Bb * Ss];
__device__ float g_wbe[Bb * Ss];
__device__ float g_y[(size_t)Tt * Ss * Bb * 600];  // [t][s][b][2H]
__device__ __half g_hT[2 * 2 * KH * Bb];     // TRANSPOSED: [dir][parity][k][b]
__device__ unsigned g_slots[NCTA_L * 8];     // per-CTA barrier slots, 32B stride

// ---------------- helpers ----------------
__device__ __forceinline__ uint32_t smem_u32(const void* p) {
    uint32_t a;
    asm("{ .reg .u64 t; cvta.to.shared.u64 t, %1; cvt.u32.u64 %0, t; }" : "=r"(a) : "l"(p));
    return a;
}
__device__ __forceinline__ void cp16(uint32_t d, const void* s) {
    asm volatile("cp.async.cg.shared.global [%0], [%1], 16;" :: "r"(d), "l"(s) : "memory");
}
__device__ __forceinline__ unsigned ldrelax(const unsigned* p) {
    unsigned x;
    asm volatile("ld.global.relaxed.gpu.u32 %0, [%1];" : "=r"(x) : "l"(p) : "memory");
    return x;
}

// ---------------- kernel 0: init ----------------
__global__ void k_init() {
    int i = threadIdx.x + blockIdx.x * blockDim.x;
    if (i < NCTA_L * 8) g_slots[i] = 0u;
    for (int e = i; e < 2 * 2 * KH * Bb; e += gridDim.x * blockDim.x)
        g_hT[e] = __float2half(0.f);
}

// ---------------- kernel 1: fused attention weights ----------------
__global__ void k_weights(const float* __restrict__ sp, const float* __restrict__ ep,
                          const float* __restrict__ cp,
                          const float* __restrict__ bsp, const float* __restrict__ bep,
                          const float* __restrict__ bcp,
                          const float* __restrict__ um, const float* __restrict__ nm,
                          const float* __restrict__ am) {
    int idx = blockIdx.x * blockDim.x + threadIdx.x;
    if (idx >= Tt * Bb * Ss) return;
    int t = idx / (Bb * Ss);
    int r = idx % (Bb * Ss);
    int b = r / Ss;
    int s = r % Ss;
    // masks are [B,T,S]
    float amv = am[(b * Tt + t) * Ss + s];
    float umv = um[(b * Tt + t) * Ss + s];
    float nmv = nm[(b * Tt + t) * Ss + s];
    const float* c = cp + (t * Bb + b) * 4;
    float wb = amv * c[0] + umv * c[1] + nmv * c[2];
    g_ws[idx] = sp[idx] * wb;
    g_we[idx] = ep[idx] * wb;
    if (t == 0) {
        const float* bc = bcp + b * 4;
        float wbb = amv * bc[0] + umv * bc[1] + nmv * bc[2];
        g_wbs[b * Ss + s] = bsp[b * Ss + s] * wbb;
        g_wbe[b * Ss + s] = bep[b * Ss + s] * wbb;
    }
}

// ---------------- kernel 2: stacked + gate-permuted fp16 Wih -----------------
__global__ void k_wpad(const float* __restrict__ wf, const float* __restrict__ wb) {
    int rrow = blockIdx.x;
    int dir = rrow >= NDIRBASE;
    int rp = dir ? rrow - NDIRBASE : rrow;
    const float* src = nullptr;
    if (rp < 1200) {
        int tile = rp >> 4, gate = (rp >> 2) & 3, cc = rp & 3;
        int srow = gate * 300 + tile * 4 + cc;
        src = (dir ? wb : wf) + (size_t)srow * K5;
    }
    __half* dst = g_W + (size_t)rrow * K5;
    for (int c = threadIdx.x * 4; c < K5; c += blockDim.x * 4) {
        float4 v = make_float4(0.f, 0.f, 0.f, 0.f);
        if (src) v = *(const float4*)(src + c);
        __half2 a = __floats2half2_rn(v.x, v.y);
        __half2 b2 = __floats2half2_rn(v.z, v.w);
        *(__half2*)(dst + c) = a;
        *(__half2*)(dst + c + 2) = b2;
    }
}

// ---------------- kernel 3: build X (fp16) ----------------
__global__ void k_xbuild(const float* __restrict__ seq) {
    int m = blockIdx.x;          // ((t*200+s)*16+b)
    int b = m & 15;
    int ts = m >> 4;
    int s = ts % Ss;
    int t = ts / Ss;
    int tp = (t > 0) ? (t - 1) : 0;
    int c = threadIdx.x * 4;     // 192 threads -> 768 cols
    const float4 sv = *(const float4*)(seq + (((size_t)(t * Bb + b) * Ss + s) * Dd) + c);
    const float4 pv = *(const float4*)(seq + (((size_t)(tp * Bb + b) * Ss + s) * Dd) + c);
    int widx = (t * Bb + b) * Ss + s;
    float w1 = g_ws[widx], w2 = g_we[widx];
    float wp1, wp2;
    if (t > 0) {
        int pidx = ((t - 1) * Bb + b) * Ss + s;
        wp1 = g_ws[pidx];
        wp2 = g_we[pidx];
    } else {
        wp1 = g_wbs[b * Ss + s];
        wp2 = g_wbe[b * Ss + s];
    }
    __half* X = g_X + (size_t)m * K5 + c;
#define R4(off, a, wgt) do { \
        __half2 _h0 = __floats2half2_rn((a).x * (wgt), (a).y * (wgt)); \
        __half2 _h1 = __floats2half2_rn((a).z * (wgt), (a).w * (wgt)); \
        *(__half2*)(X + (off)) = _h0; \
        *(__half2*)(X + (off) + 2) = _h1; } while (0)
    R4(0,    sv, 1.f);
    R4(768,  sv, w1);
    R4(1536, sv, w2);
    R4(2304, pv, wp1);
    R4(3072, pv, wp2);
#undef R4
}

// ---------------- kernel 4: pipelined fp16 wmma GEMM  C = X * W^T ------------
#define GP2 40
#define STAGEH (2 * 128 * GP2)         // halves per stage (A + B)
#define GSMEM (3 * STAGEH * 2)         // 61440 B -> 2 CTAs/SM
#define NK (K5 / 32)                   // 120 k-tiles

__global__ void __launch_bounds__(256) k_gemm2() {
    extern __shared__ __half smh[];
    int tid = threadIdx.x;
    int mt = blockIdx.y, nt = blockIdx.x;
    uint32_t sbase = smem_u32(smh);

    int wid = tid >> 5;
    int wy = wid >> 1, wx = wid & 1;   // 4x2 warps; warp tile 32x64

    int lrow0 = tid >> 2;              // 64 rows per pass, 2 passes
    int lc4 = tid & 3;                 // 4 chunks of 8 halves per row

    const __half* AG = g_X + (size_t)(mt * 128) * K5;
    const __half* BG = g_W + (size_t)(nt * 128) * K5;

    wmma::fragment<wmma::accumulator, 16, 16, 16, float> acc[2][4];
#pragma unroll
    for (int i = 0; i < 2; ++i)
#pragma unroll
        for (int j = 0; j < 4; ++j) wmma::fill_fragment(acc[i][j], 0.f);

#define LOADSTAGE(kt, st) do { \
        uint32_t sa = sbase + (st) * STAGEH * 2; \
        uint32_t sbb = sa + 128 * GP2 * 2; \
        int kof = (kt) * 32 + lc4 * 8; \
        _Pragma("unroll") \
        for (int i = 0; i < 2; ++i) { \
            int row = lrow0 + i * 64; \
            cp16(sa  + (row * GP2 + lc4 * 8) * 2, AG + (size_t)row * K5 + kof); \
            cp16(sbb + (row * GP2 + lc4 * 8) * 2, BG + (size_t)row * K5 + kof); \
        } \
        asm volatile("cp.async.commit_group;" ::: "memory"); \
    } while (0)

    LOADSTAGE(0, 0);
    LOADSTAGE(1, 1);

    for (int kt = 0; kt < NK; ++kt) {
        int st = kt % 3;
        asm volatile("cp.async.wait_group 1;" ::: "memory");
        __syncthreads();
        if (kt + 2 < NK) {
            LOADSTAGE(kt + 2, (kt + 2) % 3);
        } else {
            asm volatile("cp.async.commit_group;" ::: "memory");
        }
        const __half* As = smh + st * STAGEH;
        const __half* Bs = As + 128 * GP2;
#pragma unroll
        for (int ks = 0; ks < 2; ++ks) {
            wmma::fragment<wmma::matrix_a, 16, 16, 16, half, wmma::row_major> a0, a1;
            wmma::load_matrix_sync(a0, As + (wy * 32) * GP2 + ks * 16, GP2);
            wmma::load_matrix_sync(a1, As + (wy * 32 + 16) * GP2 + ks * 16, GP2);
#pragma unroll
            for (int j = 0; j < 4; ++j) {
                wmma::fragment<wmma::matrix_b, 16, 16, 16, half, wmma::col_major> bf;
                wmma::load_matrix_sync(bf, Bs + (wx * 64 + j * 16) * GP2 + ks * 16, GP2);
                wmma::mma_sync(acc[0][j], a0, bf, acc[0][j]);
                wmma::mma_sync(acc[1][j], a1, bf, acc[1][j]);
            }
        }
    }
#undef LOADSTAGE

#pragma unroll
    for (int i = 0; i < 2; ++i)
#pragma unroll
        for (int j = 0; j < 4; ++j) {
            float* cp = g_C + (size_t)(mt * 128 + wy * 32 + i * 16) * NPAD
                        + nt * 128 + wx * 64 + j * 16;
            wmma::store_matrix_sync(cp, acc[i][j], NPAD, wmma::mem_row_major);
        }
}

// ---------------- kernel 5: persistent bidirectional LSTM scan ----------------
// R11 dataflow + (a) warp-autonomous flag polling (no pre-MMA CTA barrier),
// (b) double-buffered accS (kills the 3rd barrier), (c) 128-thread named
// barrier for release coverage instead of a full __syncthreads.
__device__ __forceinline__ float sigm(float x) {
    return 1.f / (1.f + __expf(-x));
}
__device__ __forceinline__ float tanh_fast(float x) {
    x = fminf(fmaxf(x, -15.f), 15.f);
    float e = __expf(-2.f * x);
    return (1.f - e) / (1.f + e);
}

__global__ void __launch_bounds__(256, 1) k_lstm(
        const float* __restrict__ whf, const float* __restrict__ whb,
        const float* __restrict__ bihf, const float* __restrict__ bhhf,
        const float* __restrict__ bihb, const float* __restrict__ bhhb) {
    __shared__ __half WhhS[2 * 16 * LDW];    // prologue staging only
    __shared__ float accS[2][8 * 16 * LDA];  // DOUBLE-BUFFERED by step parity
    __shared__ float bS[32];

    int tid = threadIdx.x;
    int tile = blockIdx.x;                   // owns h-cols [4*tile, 4*tile+4)

    // prologue: stage Whh slices (gate-permuted, fp16) into shared
    for (int e = tid; e < 2 * 16 * LDW; e += 256) {
        int k = e % LDW;
        int lrr = (e / LDW) & 15;
        int dir = e / (16 * LDW);
        int gate = lrr >> 2, cc = lrr & 3;
        int srow = gate * 300 + tile * 4 + cc;
        float v = 0.f;
        if (k < 300) v = (dir ? whb : whf)[srow * 300 + k];
        WhhS[e] = __float2half(v);
    }
    if (tid < 32) {
        int dir = tid >> 4, lrr = tid & 15;
        int gate = lrr >> 2, cc = lrr & 3;
        int srow = gate * 300 + tile * 4 + cc;
        bS[tid] = dir ? (bihb[srow] + bhhb[srow]) : (bihf[srow] + bhhf[srow]);
    }
    __syncthreads();

    int wid = tid >> 5, lane = tid & 31;
    int dirw = wid >> 2, kq = wid & 3;       // warps 0-3 fwd, 4-7 bwd; k-split x4
    int edir = tid >> 6, eidx = tid & 63, ecc = eidx >> 4, eb = eidx & 15;

    // register-resident B fragments (constant across all 2000 steps)
    wmma::fragment<wmma::matrix_b, 16, 16, 16, half, wmma::col_major> Bf[5];
#pragma unroll
    for (int i = 0; i < 5; ++i)
        wmma::load_matrix_sync(Bf[i], WhhS + dirw * 16 * LDW + kq * 80 + i * 16, LDW);
    __syncthreads();

    // per-thread cell state (tid<128)
    float creg = 0.f;
    float bi = 0.f, bf2 = 0.f, bg = 0.f, bo = 0.f;
    if (tid < 128) {
        bi  = bS[edir * 16 + 0 + ecc];
        bf2 = bS[edir * 16 + 4 + ecc];
        bg  = bS[edir * 16 + 8 + ecc];
        bo  = bS[edir * 16 + 12 + ecc];
    }

    // z double buffer: prefetch step 0
    float z0 = 0.f, z1 = 0.f, z2 = 0.f, z3 = 0.f;
    float n0 = 0.f, n1 = 0.f, n2 = 0.f, n3 = 0.f;
    if (tid < 128) {
        int pos0 = edir ? (Ss - 1) : 0;
        const float* crow = g_C + ((size_t)pos0 * Bb + eb) * NPAD
                            + (edir ? NDIRBASE : 0) + tile * 16;
        n0 = crow[0 + ecc]; n1 = crow[4 + ecc]; n2 = crow[8 + ecc]; n3 = crow[12 + ecc];
    }

    // poll addresses for this lane (lane, lane+32, lane+64)
    const unsigned* p0 = g_slots + lane * 8;
    const unsigned* p1 = g_slots + (lane + 32) * 8;
    const unsigned* p2 = (lane + 64 < NCTA_L) ? (g_slots + (lane + 64) * 8) : nullptr;

    for (int g = 0; g < Tt * Ss; ++g) {
        int t = g / Ss, s = g % Ss;
        int parity = g & 1;
        int pb = g & 1;                      // accS buffer for this step
        z0 = n0; z1 = n1; z2 = n2; z3 = n3;

        // warp-autonomous poll: every warp checks all 75 flags itself
        if (g > 0) {
            unsigned tgt = (unsigned)g;
            bool ok;
            do {
                bool a = ldrelax(p0) >= tgt;
                bool b = ldrelax(p1) >= tgt;
                bool c = p2 ? (ldrelax(p2) >= tgt) : true;
                ok = __all_sync(0xFFFFFFFFu, a && b && c);
            } while (!ok);
            asm volatile("fence.acq_rel.gpu;" ::: "memory");
        }

        // recurrent matmul: A col-major from transposed g_hT, B from registers
        {
            wmma::fragment<wmma::accumulator, 16, 16, 16, float> acc;
            wmma::fill_fragment(acc, 0.f);
            const __half* hbase = g_hT + ((size_t)(dirw * 2 + parity) * KH + kq * 80) * Bb;
#pragma unroll
            for (int i = 0; i < 5; ++i) {
                wmma::fragment<wmma::matrix_a, 16, 16, 16, half, wmma::col_major> af;
                wmma::load_matrix_sync(af, hbase + i * 16 * Bb, Bb);
                wmma::mma_sync(acc, af, Bf[i], acc);
            }
            wmma::store_matrix_sync(accS[pb] + wid * 16 * LDA, acc, LDA, wmma::mem_row_major);
        }

        // prefetch next step's z
        if (tid < 128 && g + 1 < Tt * Ss) {
            int gn = g + 1;
            int tn = gn / Ss, sn = gn % Ss;
            int posn = edir ? (Ss - 1 - sn) : sn;
            const float* crow = g_C + ((size_t)(tn * Ss + posn) * Bb + eb) * NPAD
                                + (edir ? NDIRBASE : 0) + tile * 16;
            n0 = crow[0 + ecc]; n1 = crow[4 + ecc]; n2 = crow[8 + ecc]; n3 = crow[12 + ecc];
        }
        __syncthreads();   // join: all 8 warps' accS[pb] stores visible

        // gates + state update; publish h TRANSPOSED (coalesced sectors)
        float hval = 0.f;
        if (tid < 128) {
            const float* ab = accS[pb] + edir * 4 * 16 * LDA + eb * LDA;
            const int W1 = 16 * LDA, W2 = 32 * LDA, W3 = 48 * LDA;
            float zi = z0 + bi  + ab[0 + ecc]  + ab[W1 + 0 + ecc]  + ab[W2 + 0 + ecc]  + ab[W3 + 0 + ecc];
            float zf = z1 + bf2 + ab[4 + ecc]  + ab[W1 + 4 + ecc]  + ab[W2 + 4 + ecc]  + ab[W3 + 4 + ecc];
            float zg = z2 + bg  + ab[8 + ecc]  + ab[W1 + 8 + ecc]  + ab[W2 + 8 + ecc]  + ab[W3 + 8 + ecc];
            float zo = z3 + bo  + ab[12 + ecc] + ab[W1 + 12 + ecc] + ab[W2 + 12 + ecc] + ab[W3 + 12 + ecc];
            float ig = sigm(zi);
            float fg = sigm(zf);
            float gg = tanh_fast(zg);
            float og = sigm(zo);
            creg = fg * creg + ig * gg;
            hval = og * tanh_fast(creg);
            int jh = tile * 4 + ecc;
            g_hT[((size_t)(edir * 2 + (parity ^ 1)) * KH + jh) * Bb + eb] = __float2half(hval);

            // 128-thread named barrier: gate warps' h-stores done before release
            asm volatile("bar.sync 1, 128;" ::: "memory");
            if (tid == 0)
                asm volatile("st.global.release.gpu.u32 [%0], %1;"
                             :: "l"(g_slots + blockIdx.x * 8), "r"((unsigned)(g + 1)) : "memory");

            // y write AFTER release (off critical path)
            int pos = edir ? (Ss - 1 - s) : s;
            g_y[((size_t)(t * Ss + pos) * Bb + eb) * 600 + edir * 300 + jh] = hval;
        }
        // warps 4-7 proceed directly to next poll: accS double-buffered, no hazard
    }
}

// ---------------- kernel 6: classifier ----------------
__global__ void k_cls(const float* __restrict__ W, const float* __restrict__ bc,
                      float* __restrict__ out) {
    int t = blockIdx.x >> 4, b = blockIdx.x & 15;
    float a0 = 0.f, a1 = 0.f, a2 = 0.f, a3 = 0.f;
    const size_t NW = 120000;
    for (int idx = threadIdx.x; idx < (int)NW; idx += 256) {
        int s = idx / 600, c = idx % 600;
        float yv = g_y[((size_t)(t * Ss + s) * Bb + b) * 600 + c];
        yv = fmaxf(yv, 0.f);
        a0 += yv * W[idx];
        a1 += yv * W[NW + idx];
        a2 += yv * W[2 * NW + idx];
        a3 += yv * W[3 * NW + idx];
    }
#pragma unroll
    for (int off = 16; off; off >>= 1) {
        a0 += __shfl_down_sync(0xFFFFFFFFu, a0, off);
        a1 += __shfl_down_sync(0xFFFFFFFFu, a1, off);
        a2 += __shfl_down_sync(0xFFFFFFFFu, a2, off);
        a3 += __shfl_down_sync(0xFFFFFFFFu, a3, off);
    }
    __shared__ float rs[8][4];
    if ((threadIdx.x & 31) == 0) {
        int w = threadIdx.x >> 5;
        rs[w][0] = a0; rs[w][1] = a1; rs[w][2] = a2; rs[w][3] = a3;
    }
    __syncthreads();
    if (threadIdx.x < 4) {
        float sv = bc[threadIdx.x];
#pragma unroll
        for (int w = 0; w < 8; ++w) sv += rs[w][threadIdx.x];
        out[blockIdx.x * 4 + threadIdx.x] = sv;
    }
}

// ---------------- host launcher ----------------
extern "C" void kernel_launch(void* const* d_in, const int* in_sizes, int n_in,
                              void* d_out, int out_size) {
    const float* seq  = (const float*)d_in[1];
    const float* sp   = (const float*)d_in[2];
    const float* ep   = (const float*)d_in[3];
    const float* cp   = (const float*)d_in[4];
    const float* bsp  = (const float*)d_in[5];
    const float* bep  = (const float*)d_in[6];
    const float* bcp  = (const float*)d_in[7];
    const float* um   = (const float*)d_in[8];
    const float* nm   = (const float*)d_in[9];
    const float* am   = (const float*)d_in[10];
    const float* wihf = (const float*)d_in[11];
    const float* whhf = (const float*)d_in[12];
    const float* bihf = (const float*)d_in[13];
    const float* bhhf = (const float*)d_in[14];
    const float* wihb = (const float*)d_in[15];
    const float* whhb = (const float*)d_in[16];
    const float* bihb = (const float*)d_in[17];
    const float* bhhb = (const float*)d_in[18];
    const float* wcls = (const float*)d_in[19];
    const float* bcls = (const float*)d_in[20];
    float* out = (float*)d_out;

    cudaFuncSetAttribute(k_gemm2, cudaFuncAttributeMaxDynamicSharedMemorySize, GSMEM);

    k_init<<<48, 256>>>();
    k_weights<<<(Tt * Bb * Ss + 255) / 256, 256>>>(sp, ep, cp, bsp, bep, bcp, um, nm, am);
    k_wpad<<<NPAD, 256>>>(wihf, wihb);
    k_xbuild<<<Mm, 192>>>(seq);
    dim3 gg(NPAD / 128, Mm / 128);
    k_gemm2<<<gg, 256, GSMEM>>>();
    k_lstm<<<NCTA_L, 256>>>(whhf, whhb, bihf, bhhf, bihb, bhhb);
    k_cls<<<Tt * Bb, 256>>>(wcls, bcls, out);
}

// round 17
// speedup vs baseline: 3.2290x; 1.5405x over previous
#include <cuda_runtime.h>
#include <cuda_fp16.h>
#include <mma.h>
#include <cstdint>
#include <cstddef>

using namespace nvcuda;

#define Tt 10
#define Bb 16
#define Ss 200
#define Dd 768
#define K5 3840            // 5*D
#define NPAD 2432          // 1216 (fwd block) + 1216 (bwd block)
#define NDIRBASE 1216
#define Mm 32000           // T*S*B
#define KH 320             // padded recurrent K
#define LDW 344            // Whh staging stride (halves)
#define LDA 20             // accS stride (floats)
#define NCTA_L 75

// ---------------- device scratch (allocation-free) ----------------
__device__ __half g_X[(size_t)Mm * K5];      // 245.8 MB fp16
__device__ __half g_W[(size_t)NPAD * K5];    // 18.7 MB fp16
__device__ float g_C[(size_t)Mm * NPAD];     // 311.3 MB
__device__ float g_ws[Tt * Bb * Ss];
__device__ float g_we[Tt * Bb * Ss];
__device__ float g_wbs[Bb * Ss];
__device__ float g_wbe[Bb * Ss];
__device__ float g_y[(size_t)Tt * Ss * Bb * 600];  // [t][s][b][2H]
__device__ __half g_hT[2 * 2 * KH * Bb];     // TRANSPOSED: [dir][parity][k][b]
__device__ unsigned g_slots[NCTA_L * 8];     // per-CTA barrier slots, 32B stride

// ---------------- helpers ----------------
__device__ __forceinline__ uint32_t smem_u32(const void* p) {
    uint32_t a;
    asm("{ .reg .u64 t; cvta.to.shared.u64 t, %1; cvt.u32.u64 %0, t; }" : "=r"(a) : "l"(p));
    return a;
}
__device__ __forceinline__ void cp16(uint32_t d, const void* s) {
    asm volatile("cp.async.cg.shared.global [%0], [%1], 16;" :: "r"(d), "l"(s) : "memory");
}
__device__ __forceinline__ unsigned ldrelax(const unsigned* p) {
    unsigned x;
    asm volatile("ld.global.relaxed.gpu.u32 %0, [%1];" : "=r"(x) : "l"(p) : "memory");
    return x;
}
__device__ __forceinline__ uint4 ldrelax4(const uint4* p) {
    uint4 v;
    asm volatile("ld.global.relaxed.gpu.v4.u32 {%0, %1, %2, %3}, [%4];"
                 : "=r"(v.x), "=r"(v.y), "=r"(v.z), "=r"(v.w) : "l"(p) : "memory");
    return v;
}

// ---------------- kernel 0: init ----------------
__global__ void k_init() {
    int i = threadIdx.x + blockIdx.x * blockDim.x;
    if (i < NCTA_L * 8) g_slots[i] = 0u;
    for (int e = i; e < 2 * 2 * KH * Bb; e += gridDim.x * blockDim.x)
        g_hT[e] = __float2half(0.f);
}

// ---------------- kernel 1: fused attention weights ----------------
__global__ void k_weights(const float* __restrict__ sp, const float* __restrict__ ep,
                          const float* __restrict__ cp,
                          const float* __restrict__ bsp, const float* __restrict__ bep,
                          const float* __restrict__ bcp,
                          const float* __restrict__ um, const float* __restrict__ nm,
                          const float* __restrict__ am) {
    int idx = blockIdx.x * blockDim.x + threadIdx.x;
    if (idx >= Tt * Bb * Ss) return;
    int t = idx / (Bb * Ss);
    int r = idx % (Bb * Ss);
    int b = r / Ss;
    int s = r % Ss;
    // masks are [B,T,S]
    float amv = am[(b * Tt + t) * Ss + s];
    float umv = um[(b * Tt + t) * Ss + s];
    float nmv = nm[(b * Tt + t) * Ss + s];
    const float* c = cp + (t * Bb + b) * 4;
    float wb = amv * c[0] + umv * c[1] + nmv * c[2];
    g_ws[idx] = sp[idx] * wb;
    g_we[idx] = ep[idx] * wb;
    if (t == 0) {
        const float* bc = bcp + b * 4;
        float wbb = amv * bc[0] + umv * bc[1] + nmv * bc[2];
        g_wbs[b * Ss + s] = bsp[b * Ss + s] * wbb;
        g_wbe[b * Ss + s] = bep[b * Ss + s] * wbb;
    }
}

// ---------------- kernel 2: stacked + gate-permuted fp16 Wih -----------------
__global__ void k_wpad(const float* __restrict__ wf, const float* __restrict__ wb) {
    int rrow = blockIdx.x;
    int dir = rrow >= NDIRBASE;
    int rp = dir ? rrow - NDIRBASE : rrow;
    const float* src = nullptr;
    if (rp < 1200) {
        int tile = rp >> 4, gate = (rp >> 2) & 3, cc = rp & 3;
        int srow = gate * 300 + tile * 4 + cc;
        src = (dir ? wb : wf) + (size_t)srow * K5;
    }
    __half* dst = g_W + (size_t)rrow * K5;
    for (int c = threadIdx.x * 4; c < K5; c += blockDim.x * 4) {
        float4 v = make_float4(0.f, 0.f, 0.f, 0.f);
        if (src) v = *(const float4*)(src + c);
        __half2 a = __floats2half2_rn(v.x, v.y);
        __half2 b2 = __floats2half2_rn(v.z, v.w);
        *(__half2*)(dst + c) = a;
        *(__half2*)(dst + c + 2) = b2;
    }
}

// ---------------- kernel 3: build X (fp16) ----------------
__global__ void k_xbuild(const float* __restrict__ seq) {
    int m = blockIdx.x;          // ((t*200+s)*16+b)
    int b = m & 15;
    int ts = m >> 4;
    int s = ts % Ss;
    int t = ts / Ss;
    int tp = (t > 0) ? (t - 1) : 0;
    int c = threadIdx.x * 4;     // 192 threads -> 768 cols
    const float4 sv = *(const float4*)(seq + (((size_t)(t * Bb + b) * Ss + s) * Dd) + c);
    const float4 pv = *(const float4*)(seq + (((size_t)(tp * Bb + b) * Ss + s) * Dd) + c);
    int widx = (t * Bb + b) * Ss + s;
    float w1 = g_ws[widx], w2 = g_we[widx];
    float wp1, wp2;
    if (t > 0) {
        int pidx = ((t - 1) * Bb + b) * Ss + s;
        wp1 = g_ws[pidx];
        wp2 = g_we[pidx];
    } else {
        wp1 = g_wbs[b * Ss + s];
        wp2 = g_wbe[b * Ss + s];
    }
    __half* X = g_X + (size_t)m * K5 + c;
#define R4(off, a, wgt) do { \
        __half2 _h0 = __floats2half2_rn((a).x * (wgt), (a).y * (wgt)); \
        __half2 _h1 = __floats2half2_rn((a).z * (wgt), (a).w * (wgt)); \
        *(__half2*)(X + (off)) = _h0; \
        *(__half2*)(X + (off) + 2) = _h1; } while (0)
    R4(0,    sv, 1.f);
    R4(768,  sv, w1);
    R4(1536, sv, w2);
    R4(2304, pv, wp1);
    R4(3072, pv, wp2);
#undef R4
}

// ---------------- kernel 4: pipelined fp16 wmma GEMM  C = X * W^T ------------
#define GP2 40
#define STAGEH (2 * 128 * GP2)         // halves per stage (A + B)
#define GSMEM (3 * STAGEH * 2)         // 61440 B -> 2 CTAs/SM
#define NK (K5 / 32)                   // 120 k-tiles

__global__ void __launch_bounds__(256) k_gemm2() {
    extern __shared__ __half smh[];
    int tid = threadIdx.x;
    int mt = blockIdx.y, nt = blockIdx.x;
    uint32_t sbase = smem_u32(smh);

    int wid = tid >> 5;
    int wy = wid >> 1, wx = wid & 1;   // 4x2 warps; warp tile 32x64

    int lrow0 = tid >> 2;              // 64 rows per pass, 2 passes
    int lc4 = tid & 3;                 // 4 chunks of 8 halves per row

    const __half* AG = g_X + (size_t)(mt * 128) * K5;
    const __half* BG = g_W + (size_t)(nt * 128) * K5;

    wmma::fragment<wmma::accumulator, 16, 16, 16, float> acc[2][4];
#pragma unroll
    for (int i = 0; i < 2; ++i)
#pragma unroll
        for (int j = 0; j < 4; ++j) wmma::fill_fragment(acc[i][j], 0.f);

#define LOADSTAGE(kt, st) do { \
        uint32_t sa = sbase + (st) * STAGEH * 2; \
        uint32_t sbb = sa + 128 * GP2 * 2; \
        int kof = (kt) * 32 + lc4 * 8; \
        _Pragma("unroll") \
        for (int i = 0; i < 2; ++i) { \
            int row = lrow0 + i * 64; \
            cp16(sa  + (row * GP2 + lc4 * 8) * 2, AG + (size_t)row * K5 + kof); \
            cp16(sbb + (row * GP2 + lc4 * 8) * 2, BG + (size_t)row * K5 + kof); \
        } \
        asm volatile("cp.async.commit_group;" ::: "memory"); \
    } while (0)

    LOADSTAGE(0, 0);
    LOADSTAGE(1, 1);

    for (int kt = 0; kt < NK; ++kt) {
        int st = kt % 3;
        asm volatile("cp.async.wait_group 1;" ::: "memory");
        __syncthreads();
        if (kt + 2 < NK) {
            LOADSTAGE(kt + 2, (kt + 2) % 3);
        } else {
            asm volatile("cp.async.commit_group;" ::: "memory");
        }
        const __half* As = smh + st * STAGEH;
        const __half* Bs = As + 128 * GP2;
#pragma unroll
        for (int ks = 0; ks < 2; ++ks) {
            wmma::fragment<wmma::matrix_a, 16, 16, 16, half, wmma::row_major> a0, a1;
            wmma::load_matrix_sync(a0, As + (wy * 32) * GP2 + ks * 16, GP2);
            wmma::load_matrix_sync(a1, As + (wy * 32 + 16) * GP2 + ks * 16, GP2);
#pragma unroll
            for (int j = 0; j < 4; ++j) {
                wmma::fragment<wmma::matrix_b, 16, 16, 16, half, wmma::col_major> bf;
                wmma::load_matrix_sync(bf, Bs + (wx * 64 + j * 16) * GP2 + ks * 16, GP2);
                wmma::mma_sync(acc[0][j], a0, bf, acc[0][j]);
                wmma::mma_sync(acc[1][j], a1, bf, acc[1][j]);
            }
        }
    }
#undef LOADSTAGE

#pragma unroll
    for (int i = 0; i < 2; ++i)
#pragma unroll
        for (int j = 0; j < 4; ++j) {
            float* cp = g_C + (size_t)(mt * 128 + wy * 32 + i * 16) * NPAD
                        + nt * 128 + wx * 64 + j * 16;
            wmma::store_matrix_sync(cp, acc[i][j], NPAD, wmma::mem_row_major);
        }
}

// ---------------- kernel 5: persistent bidirectional LSTM scan ----------------
// R11 protocol exactly (poll by tid<75, __syncthreads, release after barrier,
// transposed h, deferred y). ONE change: A-slices are fetched with L1-bypassing
// ld.relaxed.gpu vector loads into per-warp smem staging -> the per-step
// fence.acq_rel.gpu (= CCTL.IVALL L1 flush x2000) is eliminated entirely.
__device__ __forceinline__ float sigm(float x) {
    return 1.f / (1.f + __expf(-x));
}
__device__ __forceinline__ float tanh_fast(float x) {
    x = fminf(fmaxf(x, -15.f), 15.f);
    float e = __expf(-2.f * x);
    return (1.f - e) / (1.f + e);
}

__global__ void __launch_bounds__(256, 1) k_lstm(
        const float* __restrict__ whf, const float* __restrict__ whb,
        const float* __restrict__ bihf, const float* __restrict__ bhhf,
        const float* __restrict__ bihb, const float* __restrict__ bhhb) {
    // smww: prologue Whh staging (22016 B), reused after prologue as the
    // per-warp A staging area (needs 8*1280 halves = 20480 B).
    __shared__ __align__(16) __half smww[2 * 16 * LDW];
    __shared__ float accS[8 * 16 * LDA];
    __shared__ float bS[32];

    int tid = threadIdx.x;
    int tile = blockIdx.x;                   // owns h-cols [4*tile, 4*tile+4)

    // prologue: stage Whh slices (gate-permuted, fp16) into shared
    for (int e = tid; e < 2 * 16 * LDW; e += 256) {
        int k = e % LDW;
        int lrr = (e / LDW) & 15;
        int dir = e / (16 * LDW);
        int gate = lrr >> 2, cc = lrr & 3;
        int srow = gate * 300 + tile * 4 + cc;
        float v = 0.f;
        if (k < 300) v = (dir ? whb : whf)[srow * 300 + k];
        smww[e] = __float2half(v);
    }
    if (tid < 32) {
        int dir = tid >> 4, lrr = tid & 15;
        int gate = lrr >> 2, cc = lrr & 3;
        int srow = gate * 300 + tile * 4 + cc;
        bS[tid] = dir ? (bihb[srow] + bhhb[srow]) : (bihf[srow] + bhhf[srow]);
    }
    __syncthreads();

    int wid = tid >> 5, lane = tid & 31;
    int dirw = wid >> 2, kq = wid & 3;       // warps 0-3 fwd, 4-7 bwd; k-split x4
    int edir = tid >> 6, eidx = tid & 63, ecc = eidx >> 4, eb = eidx & 15;

    // register-resident B fragments (constant across all 2000 steps)
    wmma::fragment<wmma::matrix_b, 16, 16, 16, half, wmma::col_major> Bf[5];
#pragma unroll
    for (int i = 0; i < 5; ++i)
        wmma::load_matrix_sync(Bf[i], smww + dirw * 16 * LDW + kq * 80 + i * 16, LDW);
    __syncthreads();   // Whh consumed -> smww becomes A staging

    __half* stg = smww + wid * 1280;         // per-warp [80 k][16 b] halves

    // per-thread cell state (tid<128)
    float creg = 0.f;
    float bi = 0.f, bf2 = 0.f, bg = 0.f, bo = 0.f;
    if (tid < 128) {
        bi  = bS[edir * 16 + 0 + ecc];
        bf2 = bS[edir * 16 + 4 + ecc];
        bg  = bS[edir * 16 + 8 + ecc];
        bo  = bS[edir * 16 + 12 + ecc];
    }

    // z double buffer: prefetch step 0
    float z0 = 0.f, z1 = 0.f, z2 = 0.f, z3 = 0.f;
    float n0 = 0.f, n1 = 0.f, n2 = 0.f, n3 = 0.f;
    if (tid < 128) {
        int pos0 = edir ? (Ss - 1) : 0;
        const float* crow = g_C + ((size_t)pos0 * Bb + eb) * NPAD
                            + (edir ? NDIRBASE : 0) + tile * 16;
        n0 = crow[0 + ecc]; n1 = crow[4 + ecc]; n2 = crow[8 + ecc]; n3 = crow[12 + ecc];
    }

    for (int g = 0; g < Tt * Ss; ++g) {
        int t = g / Ss, s = g % Ss;
        int parity = g & 1;
        z0 = n0; z1 = n1; z2 = n2; z3 = n3;

        // wait: all 75 CTAs published step g-1 (R11 protocol, NO fence needed:
        // the h loads below are L2-direct relaxed loads)
        if (g > 0) {
            if (tid < NCTA_L) {
                unsigned f;
                do {
                    f = ldrelax(g_slots + tid * 8);
                } while (f < (unsigned)g);
            }
            __syncthreads();
        }

        // fetch this warp's A slice (contiguous 2560B) L2-direct into staging
        {
            const uint4* src = (const uint4*)(g_hT
                + ((size_t)(dirw * 2 + parity) * KH + kq * 80) * Bb);
            uint4* dst = (uint4*)stg;
#pragma unroll
            for (int i = 0; i < 5; ++i)
                dst[i * 32 + lane] = ldrelax4(src + i * 32 + lane);
            __syncwarp();
        }

        // recurrent matmul: A col-major from staging (ldm=16), B from registers
        {
            wmma::fragment<wmma::accumulator, 16, 16, 16, float> acc;
            wmma::fill_fragment(acc, 0.f);
#pragma unroll
            for (int i = 0; i < 5; ++i) {
                wmma::fragment<wmma::matrix_a, 16, 16, 16, half, wmma::col_major> af;
                wmma::load_matrix_sync(af, stg + i * 256, 16);
                wmma::mma_sync(acc, af, Bf[i], acc);
            }
            wmma::store_matrix_sync(accS + wid * 16 * LDA, acc, LDA, wmma::mem_row_major);
        }

        // prefetch next step's z (generic loads; g_C is constant during scan)
        if (tid < 128 && g + 1 < Tt * Ss) {
            int gn = g + 1;
            int tn = gn / Ss, sn = gn % Ss;
            int posn = edir ? (Ss - 1 - sn) : sn;
            const float* crow = g_C + ((size_t)(tn * Ss + posn) * Bb + eb) * NPAD
                                + (edir ? NDIRBASE : 0) + tile * 16;
            n0 = crow[0 + ecc]; n1 = crow[4 + ecc]; n2 = crow[8 + ecc]; n3 = crow[12 + ecc];
        }
        __syncthreads();   // accS visible to gate threads

        // gates + state update; publish h TRANSPOSED (coalesced sectors)
        float hval = 0.f;
        if (tid < 128) {
            const float* ab = accS + edir * 4 * 16 * LDA + eb * LDA;
            const int W1 = 16 * LDA, W2 = 32 * LDA, W3 = 48 * LDA;
            float zi = z0 + bi  + ab[0 + ecc]  + ab[W1 + 0 + ecc]  + ab[W2 + 0 + ecc]  + ab[W3 + 0 + ecc];
            float zf = z1 + bf2 + ab[4 + ecc]  + ab[W1 + 4 + ecc]  + ab[W2 + 4 + ecc]  + ab[W3 + 4 + ecc];
            float zg = z2 + bg  + ab[8 + ecc]  + ab[W1 + 8 + ecc]  + ab[W2 + 8 + ecc]  + ab[W3 + 8 + ecc];
            float zo = z3 + bo  + ab[12 + ecc] + ab[W1 + 12 + ecc] + ab[W2 + 12 + ecc] + ab[W3 + 12 + ecc];
            float ig = sigm(zi);
            float fg = sigm(zf);
            float gg = tanh_fast(zg);
            float og = sigm(zo);
            creg = fg * creg + ig * gg;
            hval = og * tanh_fast(creg);
            int jh = tile * 4 + ecc;
            g_hT[((size_t)(edir * 2 + (parity ^ 1)) * KH + jh) * Bb + eb] = __float2half(hval);
        }
        __syncthreads();

        // publish (release after barrier covers all g_hT stores of this CTA),
        // THEN the y write — excluded from the release drain on purpose.
        if (tid == 0)
            asm volatile("st.global.release.gpu.u32 [%0], %1;"
                         :: "l"(g_slots + blockIdx.x * 8), "r"((unsigned)(g + 1)) : "memory");
        if (tid < 128) {
            int pos = edir ? (Ss - 1 - s) : s;
            int jh = tile * 4 + ecc;
            g_y[((size_t)(t * Ss + pos) * Bb + eb) * 600 + edir * 300 + jh] = hval;
        }
    }
}

// ---------------- kernel 6: classifier ----------------
__global__ void k_cls(const float* __restrict__ W, const float* __restrict__ bc,
                      float* __restrict__ out) {
    int t = blockIdx.x >> 4, b = blockIdx.x & 15;
    float a0 = 0.f, a1 = 0.f, a2 = 0.f, a3 = 0.f;
    const size_t NW = 120000;
    for (int idx = threadIdx.x; idx < (int)NW; idx += 256) {
        int s = idx / 600, c = idx % 600;
        float yv = g_y[((size_t)(t * Ss + s) * Bb + b) * 600 + c];
        yv = fmaxf(yv, 0.f);
        a0 += yv * W[idx];
        a1 += yv * W[NW + idx];
        a2 += yv * W[2 * NW + idx];
        a3 += yv * W[3 * NW + idx];
    }
#pragma unroll
    for (int off = 16; off; off >>= 1) {
        a0 += __shfl_down_sync(0xFFFFFFFFu, a0, off);
        a1 += __shfl_down_sync(0xFFFFFFFFu, a1, off);
        a2 += __shfl_down_sync(0xFFFFFFFFu, a2, off);
        a3 += __shfl_down_sync(0xFFFFFFFFu, a3, off);
    }
    __shared__ float rs[8][4];
    if ((threadIdx.x & 31) == 0) {
        int w = threadIdx.x >> 5;
        rs[w][0] = a0; rs[w][1] = a1; rs[w][2] = a2; rs[w][3] = a3;
    }
    __syncthreads();
    if (threadIdx.x < 4) {
        float sv = bc[threadIdx.x];
#pragma unroll
        for (int w = 0; w < 8; ++w) sv += rs[w][threadIdx.x];
        out[blockIdx.x * 4 + threadIdx.x] = sv;
    }
}

// ---------------- host launcher ----------------
extern "C" void kernel_launch(void* const* d_in, const int* in_sizes, int n_in,
                              void* d_out, int out_size) {
    const float* seq  = (const float*)d_in[1];
    const float* sp   = (const float*)d_in[2];
    const float* ep   = (const float*)d_in[3];
    const float* cp   = (const float*)d_in[4];
    const float* bsp  = (const float*)d_in[5];
    const float* bep  = (const float*)d_in[6];
    const float* bcp  = (const float*)d_in[7];
    const float* um   = (const float*)d_in[8];
    const float* nm   = (const float*)d_in[9];
    const float* am   = (const float*)d_in[10];
    const float* wihf = (const float*)d_in[11];
    const float* whhf = (const float*)d_in[12];
    const float* bihf = (const float*)d_in[13];
    const float* bhhf = (const float*)d_in[14];
    const float* wihb = (const float*)d_in[15];
    const float* whhb = (const float*)d_in[16];
    const float* bihb = (const float*)d_in[17];
    const float* bhhb = (const float*)d_in[18];
    const float* wcls = (const float*)d_in[19];
    const float* bcls = (const float*)d_in[20];
    float* out = (float*)d_out;

    cudaFuncSetAttribute(k_gemm2, cudaFuncAttributeMaxDynamicSharedMemorySize, GSMEM);

    k_init<<<48, 256>>>();
    k_weights<<<(Tt * Bb * Ss + 255) / 256, 256>>>(sp, ep, cp, bsp, bep, bcp, um, nm, am);
    k_wpad<<<NPAD, 256>>>(wihf, wihb);
    k_xbuild<<<Mm, 192>>>(seq);
    dim3 gg(NPAD / 128, Mm / 128);
    k_gemm2<<<gg, 256, GSMEM>>>();
    k_lstm<<<NCTA_L, 256>>>(whhf, whhb, bihf, bhhf, bihb, bhhb);
    k_cls<<<Tt * Bb, 256>>>(wcls, bcls, out);
}